// round 4
// baseline (speedup 1.0000x reference)
#include <cuda_runtime.h>
#include <math.h>

#define NROW 4096          // 64*64 legality cells per board
#define QDIM 256           // quality vector length
#define NEG_FILL -1000000.0f
#define EOS_COEF 0.25f
#define MAXROWS 8192
#define MAXBLK 16384

// Scratch (static __device__ globals — no allocation)
__device__ unsigned g_maskT[(size_t)MAXROWS * NROW / 32];   // 4 MB
__device__ unsigned g_maskP[(size_t)MAXROWS * NROW / 32];   // 4 MB
__device__ float    g_bce[MAXBLK];
__device__ float    g_ce[MAXBLK];
__device__ float    g_mse[MAXBLK];
__device__ unsigned g_count;   // zero-init; last block resets to 0

// ---------------- kernel 1: pure streaming ----------------
// Each thread owns 32 contiguous cells (8 float4 from each array).
__global__ __launch_bounds__(256) void stream_kernel(
    const float4* __restrict__ pl4,   // pred_legal as float4
    const float4* __restrict__ tl4,   // target_legal as float4
    float* __restrict__ gbce)
{
    const int tid = blockIdx.x * 256 + threadIdx.x;
    const float4* P = pl4 + (size_t)tid * 8;
    const float4* T = tl4 + (size_t)tid * 8;

    unsigned mT = 0u, mP = 0u;
    float acc = 0.f;
    #pragma unroll
    for (int k = 0; k < 8; k++) {
        float4 pv = P[k];
        float4 tv = T[k];
        float px[4] = {pv.x, pv.y, pv.z, pv.w};
        float tx[4] = {tv.x, tv.y, tv.z, tv.w};
        #pragma unroll
        for (int j = 0; j < 4; j++) {
            float x = px[j], tg = tx[j];
            float sp  = __logf(1.f + __expf(-fabsf(x)));   // softplus(-|x|)
            float bce = fmaxf(x, 0.f) - x * tg + sp;
            acc += (tg == 0.f ? EOS_COEF : 1.f) * bce;
            int bit = k * 4 + j;
            if (tg == 1.f) mT |= (1u << bit);
            if (x  > 0.f)  mP |= (1u << bit);
        }
    }
    g_maskT[tid] = mT;
    g_maskP[tid] = mP;

    // single block reduction of the BCE partial
    __shared__ float red[8];
    int lane = threadIdx.x & 31, warp = threadIdx.x >> 5;
    #pragma unroll
    for (int o = 16; o; o >>= 1) acc += __shfl_down_sync(0xffffffffu, acc, o);
    if (lane == 0) red[warp] = acc;
    __syncthreads();
    if (warp == 0) {
        acc = (lane < 8) ? red[lane] : 0.f;
        #pragma unroll
        for (int o = 4; o; o >>= 1) acc += __shfl_down_sync(0xffffffffu, acc, o);
        if (lane == 0) gbce[blockIdx.x] = acc;
    }
}

// ---- warp reduce helpers (all-lanes result) ----
__device__ __forceinline__ float warpSum(float v) {
    #pragma unroll
    for (int o = 16; o; o >>= 1) v += __shfl_xor_sync(0xffffffffu, v, o);
    return v;
}
__device__ __forceinline__ float warpMax(float v) {
    #pragma unroll
    for (int o = 16; o; o >>= 1) v = fmaxf(v, __shfl_xor_sync(0xffffffffu, v, o));
    return v;
}

__device__ __forceinline__ double blockReduceSumD(double v, double* shd) {
    int lane = threadIdx.x & 31, warp = threadIdx.x >> 5;
    #pragma unroll
    for (int o = 16; o; o >>= 1) v += __shfl_down_sync(0xffffffffu, v, o);
    if (lane == 0) shd[warp] = v;
    __syncthreads();
    if (warp == 0) {
        v = (lane < 8) ? shd[lane] : 0.0;
        #pragma unroll
        for (int o = 4; o; o >>= 1) v += __shfl_down_sync(0xffffffffu, v, o);
        if (lane == 0) shd[0] = v;
    }
    __syncthreads();
    double r = shd[0];
    __syncthreads();
    return r;
}

// ---------------- kernel 2: lineup + CE/MSE, one WARP per row ----------------
__global__ __launch_bounds__(256) void lineup_kernel(
    const float* __restrict__ pred_q,     // [B, 256]
    const float* __restrict__ target_q,   // [B, 256]
    float* __restrict__ out, int B, int nblk1, int nblk2)
{
    const int w = threadIdx.x >> 5, l = threadIdx.x & 31;
    const int b = blockIdx.x * 8 + w;

    __shared__ float lined[8][QDIM];
    __shared__ unsigned char match[8][QDIM];
    __shared__ float rowCe[8], rowMse[8];
    __shared__ unsigned lastFlag;

    // load this row's masks: 128 words, 4 per lane (coalesced uint4)
    const uint4* mt4 = (const uint4*)(g_maskT + (size_t)b * (NROW / 32));
    const uint4* mp4 = (const uint4*)(g_maskP + (size_t)b * (NROW / 32));
    uint4 WT = mt4[l], WP = mp4[l];
    unsigned wT[4] = {WT.x, WT.y, WT.z, WT.w};
    unsigned wP[4] = {WP.x, WP.y, WP.z, WP.w};

    #pragma unroll
    for (int j = 0; j < 8; j++) {
        lined[w][l * 8 + j] = NEG_FILL;
        match[w][l * 8 + j] = 0;
    }

    int cT = 0, cP = 0;
    #pragma unroll
    for (int k = 0; k < 4; k++) { cT += __popc(wT[k]); cP += __popc(wP[k]); }
    int sT = cT, sP = cP;   // warp-inclusive scans
    #pragma unroll
    for (int o = 1; o < 32; o <<= 1) {
        int vT = __shfl_up_sync(0xffffffffu, sT, o);
        int vP = __shfl_up_sync(0xffffffffu, sP, o);
        if (l >= o) { sT += vT; sP += vP; }
    }
    int tIdx  = sT - cT;   // exclusive target rank at my first cell
    int pBase = sP - cP;   // exclusive pred rank at my first cell
    __syncwarp();

    const float* pq = pred_q + (size_t)b * QDIM;
    #pragma unroll
    for (int k = 0; k < 4; k++) {
        unsigned m = wT[k], p = wP[k];
        while (m) {
            int bit = __ffs(m) - 1;
            m &= m - 1;
            if ((p >> bit) & 1u) {
                int pi = pBase + __popc(p & ((1u << bit) - 1u));
                if (pi < QDIM - 1 && tIdx < QDIM - 1) {
                    lined[w][tIdx] = __ldg(pq + pi);
                    match[w][tIdx] = 1;
                }
            }
            tIdx++;
        }
        pBase += __popc(p);
    }
    __syncwarp();

    // logsumexp over lined[0..254] (max-shift REQUIRED: rows with no matches
    // are all-NEG_FILL and must produce finite lse like the reference)
    float vals[8];
    float mx = -INFINITY;
    #pragma unroll
    for (int j = 0; j < 8; j++) {
        vals[j] = lined[w][l * 8 + j];
        mx = fmaxf(mx, vals[j]);    // incl. slot 255 (also NEG_FILL; harmless)
    }
    mx = warpMax(mx);
    float es = 0.f;
    #pragma unroll
    for (int j = 0; j < 8; j++)
        if (l * 8 + j < QDIM - 1) es += __expf(vals[j] - mx);
    es = warpSum(es);
    float lse = mx + __logf(es);

    // CE terms over columns 0..254
    const float4* tq4 = (const float4*)(target_q + (size_t)b * QDIM);
    float4 A = tq4[l * 2], C = tq4[l * 2 + 1];
    float tq[8] = {A.x, A.y, A.z, A.w, C.x, C.y, C.z, C.w};
    float wsum = 0.f, dot = 0.f;
    #pragma unroll
    for (int j = 0; j < 8; j++) {
        int idx = l * 8 + j;
        if (idx < QDIM - 1) {
            float wq = tq[j] * (float)match[w][idx];
            wsum += wq;
            dot  += wq * (vals[j] - lse);
        }
    }
    wsum = warpSum(wsum);
    dot  = warpSum(dot);
    float tq255 = __shfl_sync(0xffffffffu, C.w, 31);

    if (l == 0) {
        float ce = -dot / (wsum + 1e-10f);
        float dq = __ldg(pq + QDIM - 1) - tq255;
        rowCe[w]  = ce;
        rowMse[w] = dq * dq;
    }
    __syncthreads();
    if (threadIdx.x == 0) {
        float ce = 0.f, ms = 0.f;
        #pragma unroll
        for (int i = 0; i < 8; i++) { ce += rowCe[i]; ms += rowMse[i]; }
        g_ce[blockIdx.x]  = ce;
        g_mse[blockIdx.x] = ms;
        __threadfence();
        unsigned old = atomicAdd(&g_count, 1u);
        lastFlag = (old == (unsigned)(nblk2 - 1)) ? 1u : 0u;
    }
    __syncthreads();

    // last block: final scalar reduce
    if (lastFlag) {
        __threadfence();
        __shared__ double shd[8];
        double sLab = 0.0, sCe = 0.0, sMse = 0.0;
        for (int i = threadIdx.x; i < nblk1; i += 256) sLab += (double)g_bce[i];
        for (int i = threadIdx.x; i < nblk2; i += 256) {
            sCe  += (double)g_ce[i];
            sMse += (double)g_mse[i];
        }
        sLab = blockReduceSumD(sLab, shd);
        sCe  = blockReduceSumD(sCe,  shd);
        sMse = blockReduceSumD(sMse, shd);
        if (threadIdx.x == 0) {
            double loss_labels = sLab / ((double)B * (double)NROW);
            double loss_ce     = sCe / (double)(QDIM - 1);
            double loss_mse    = sMse / (double)B;
            out[0] = (float)loss_labels;
            out[1] = (float)(loss_ce * 200.0 + loss_mse);
            g_count = 0;   // reset for next graph replay
        }
    }
}

extern "C" void kernel_launch(void* const* d_in, const int* in_sizes, int n_in,
                              void* d_out, int out_size) {
    const float* pred_legal   = (const float*)d_in[0];
    const float* pred_q       = (const float*)d_in[1];
    const float* target_legal = (const float*)d_in[2];
    const float* target_q     = (const float*)d_in[3];
    float* out = (float*)d_out;

    int B = in_sizes[1] / QDIM;            // 4096
    int nblk1 = (B * NROW / 32) / 256;     // 2048: streaming blocks
    int nblk2 = B / 8;                     // 512: lineup blocks (8 rows each)

    stream_kernel<<<nblk1, 256>>>((const float4*)pred_legal,
                                  (const float4*)target_legal, g_bce);
    lineup_kernel<<<nblk2, 256>>>(pred_q, target_q, out, B, nblk1, nblk2);
}

// round 5
// speedup vs baseline: 1.0429x; 1.0429x over previous
#include <cuda_runtime.h>
#include <math.h>

#define NROW 4096          // 64*64 legality cells per board
#define QDIM 256           // quality vector length
#define NEG_FILL -1000000.0f
#define EOS_COEF 0.25f
#define MAXROWS 8192

// Per-row partials + ticket (static globals — no allocation)
__device__ float    g_lab[MAXROWS];
__device__ float    g_ce [MAXROWS];
__device__ float    g_mse[MAXROWS];
__device__ unsigned g_count;   // zero-init; last block resets to 0

// spread 8 bits to every 4th bit position (bit i -> bit 4i)
__device__ __forceinline__ unsigned spread4(unsigned x) {
    x = (x | (x << 12)) & 0x000F000Fu;
    x = (x | (x << 6))  & 0x03030303u;
    x = (x | (x << 3))  & 0x11111111u;
    return x;
}

__device__ __forceinline__ float warpSum(float v) {
    #pragma unroll
    for (int o = 16; o; o >>= 1) v += __shfl_xor_sync(0xffffffffu, v, o);
    return v;
}
__device__ __forceinline__ float warpMax(float v) {
    #pragma unroll
    for (int o = 16; o; o >>= 1) v = fmaxf(v, __shfl_xor_sync(0xffffffffu, v, o));
    return v;
}
__device__ __forceinline__ double blockReduceSumD(double v, double* shd) {
    int lane = threadIdx.x & 31, warp = threadIdx.x >> 5;
    #pragma unroll
    for (int o = 16; o; o >>= 1) v += __shfl_down_sync(0xffffffffu, v, o);
    if (lane == 0) shd[warp] = v;
    __syncthreads();
    if (warp == 0) {
        v = (lane < 8) ? shd[lane] : 0.0;
        #pragma unroll
        for (int o = 4; o; o >>= 1) v += __shfl_down_sync(0xffffffffu, v, o);
        if (lane == 0) shd[0] = v;
    }
    __syncthreads();
    double r = shd[0];
    __syncthreads();
    return r;
}

// One block per batch row. 8 warps stream 512 elements each (coalesced),
// masks built via ballot into shared; warp 0 then does the lineup.
__global__ __launch_bounds__(256) void crit_kernel(
    const float4* __restrict__ pl4,   // pred_legal  [B*1024] float4
    const float4* __restrict__ tl4,   // target_legal[B*1024] float4
    const float4* __restrict__ pq4,   // pred_q      [B*64]   float4
    const float4* __restrict__ tq4,   // target_q    [B*64]   float4
    float* __restrict__ out, int B)
{
    const int b = blockIdx.x;
    const int w = threadIdx.x >> 5, l = threadIdx.x & 31;

    __shared__ unsigned maskT[128], maskP[128];   // ballot-order words
    __shared__ float pqs[QDIM], tqs[QDIM];
    __shared__ float lined[QDIM];
    __shared__ unsigned char match[QDIM];
    __shared__ float red[8];
    __shared__ double shd[8];
    __shared__ float rowStats[3];
    __shared__ unsigned lastFlag;

    // stage quality rows into shared (first 128 threads, coalesced float4)
    if (threadIdx.x < 64)
        ((float4*)pqs)[threadIdx.x] = pq4[(size_t)b * 64 + threadIdx.x];
    else if (threadIdx.x < 128)
        ((float4*)tqs)[threadIdx.x - 64] = tq4[(size_t)b * 64 + (threadIdx.x - 64)];

    // ---- streaming: warp w covers elements [512w, 512w+512) of row b ----
    float acc = 0.f;
    const size_t rowBase = (size_t)b * 1024 + (size_t)w * 128;
    #pragma unroll
    for (int i = 0; i < 4; i++) {
        float4 pv = __ldg(pl4 + rowBase + i * 32 + l);   // coalesced: lane-adjacent
        float4 tv = __ldg(tl4 + rowBase + i * 32 + l);
        float px[4] = {pv.x, pv.y, pv.z, pv.w};
        float tx[4] = {tv.x, tv.y, tv.z, tv.w};
        bool pt[4], pp[4];
        #pragma unroll
        for (int j = 0; j < 4; j++) {
            float x = px[j], tg = tx[j];
            float sp  = __logf(1.f + __expf(-fabsf(x)));   // fast ok in BCE (R3)
            float bce = fmaxf(x, 0.f) - x * tg + sp;
            acc += (tg == 0.f ? EOS_COEF : 1.f) * bce;
            pt[j] = (tg == 1.f);
            pp[j] = (x  > 0.f);
        }
        // ballot word j: bit l = element (chunkBase + 4l + j)
        unsigned bT0 = __ballot_sync(0xffffffffu, pt[0]);
        unsigned bT1 = __ballot_sync(0xffffffffu, pt[1]);
        unsigned bT2 = __ballot_sync(0xffffffffu, pt[2]);
        unsigned bT3 = __ballot_sync(0xffffffffu, pt[3]);
        unsigned bP0 = __ballot_sync(0xffffffffu, pp[0]);
        unsigned bP1 = __ballot_sync(0xffffffffu, pp[1]);
        unsigned bP2 = __ballot_sync(0xffffffffu, pp[2]);
        unsigned bP3 = __ballot_sync(0xffffffffu, pp[3]);
        int base = w * 16 + i * 4;
        if (l < 4) {
            unsigned vT = (l == 0) ? bT0 : (l == 1) ? bT1 : (l == 2) ? bT2 : bT3;
            maskT[base + l] = vT;
        } else if (l < 8) {
            int j = l - 4;
            unsigned vP = (j == 0) ? bP0 : (j == 1) ? bP1 : (j == 2) ? bP2 : bP3;
            maskP[base + j] = vP;
        }
    }
    // per-warp BCE partial
    acc = warpSum(acc);
    if (l == 0) red[w] = acc;
    __syncthreads();

    // ---- lineup: warp 0 only; other warps wait at the final barrier ----
    if (w == 0) {
        // lane l owns chunk l (elements [128l, 128l+128)): 4 ballot words each
        uint4 WT = ((const uint4*)maskT)[l];
        uint4 WP = ((const uint4*)maskP)[l];

        #pragma unroll
        for (int j = 0; j < 8; j++) {
            lined[l * 8 + j] = NEG_FILL;
            match[l * 8 + j] = 0;
        }

        // transpose ballot-order -> row-major words mT[0..3], mP[0..3]
        unsigned mT[4], mP[4];
        #pragma unroll
        for (int k = 0; k < 4; k++) {
            unsigned s = 8 * k;
            mT[k] = spread4((WT.x >> s) & 0xFFu)
                  | (spread4((WT.y >> s) & 0xFFu) << 1)
                  | (spread4((WT.z >> s) & 0xFFu) << 2)
                  | (spread4((WT.w >> s) & 0xFFu) << 3);
            mP[k] = spread4((WP.x >> s) & 0xFFu)
                  | (spread4((WP.y >> s) & 0xFFu) << 1)
                  | (spread4((WP.z >> s) & 0xFFu) << 2)
                  | (spread4((WP.w >> s) & 0xFFu) << 3);
        }

        int cT = 0, cP = 0;
        #pragma unroll
        for (int k = 0; k < 4; k++) { cT += __popc(mT[k]); cP += __popc(mP[k]); }
        int sT = cT, sP = cP;   // warp-inclusive scans
        #pragma unroll
        for (int o = 1; o < 32; o <<= 1) {
            int vT = __shfl_up_sync(0xffffffffu, sT, o);
            int vP = __shfl_up_sync(0xffffffffu, sP, o);
            if (l >= o) { sT += vT; sP += vP; }
        }
        int tIdx  = sT - cT;   // exclusive target rank at chunk start
        int pBase = sP - cP;   // exclusive pred rank at chunk start
        __syncwarp();

        // sparse scatter (ranks unique -> plain stores), gather from shared pq
        #pragma unroll
        for (int k = 0; k < 4; k++) {
            unsigned m = mT[k], p = mP[k];
            while (m) {
                int bit = __ffs(m) - 1;
                m &= m - 1;
                if ((p >> bit) & 1u) {
                    int pi = pBase + __popc(p & ((1u << bit) - 1u));
                    if (pi < QDIM - 1 && tIdx < QDIM - 1) {
                        lined[tIdx] = pqs[pi];
                        match[tIdx] = 1;
                    }
                }
                tIdx++;
            }
            pBase += __popc(p);
        }
        __syncwarp();

        // logsumexp over lined[0..254] — PRECISE expf/logf (CE is x200 sensitive)
        float vals[8];
        float mx = -INFINITY;
        #pragma unroll
        for (int j = 0; j < 8; j++) {
            vals[j] = lined[l * 8 + j];
            mx = fmaxf(mx, vals[j]);        // slot 255 is NEG_FILL: harmless
        }
        mx = warpMax(mx);
        float es = 0.f;
        #pragma unroll
        for (int j = 0; j < 8; j++)
            if (l * 8 + j < QDIM - 1) es += expf(vals[j] - mx);
        es = warpSum(es);
        float lse = mx + logf(es);

        float wsum = 0.f, dot = 0.f;
        #pragma unroll
        for (int j = 0; j < 8; j++) {
            int idx = l * 8 + j;
            if (idx < QDIM - 1) {
                float wq = tqs[idx] * (float)match[idx];
                wsum += wq;
                dot  += wq * (vals[j] - lse);
            }
        }
        wsum = warpSum(wsum);
        dot  = warpSum(dot);

        if (l == 0) {
            float ce = -dot / (wsum + 1e-10f);
            float dq = pqs[QDIM - 1] - tqs[QDIM - 1];
            float lab = 0.f;
            #pragma unroll
            for (int i = 0; i < 8; i++) lab += red[i];
            g_lab[b] = lab;
            g_ce [b] = ce;
            g_mse[b] = dq * dq;
            __threadfence();
            unsigned old = atomicAdd(&g_count, 1u);
            lastFlag = (old == (unsigned)(B - 1)) ? 1u : 0u;
        }
    }
    __syncthreads();

    // ---- last block: final scalar reduce ----
    if (lastFlag) {
        __threadfence();
        double sLab = 0.0, sCe = 0.0, sMse = 0.0;
        for (int i = threadIdx.x; i < B; i += 256) {
            sLab += (double)g_lab[i];
            sCe  += (double)g_ce[i];
            sMse += (double)g_mse[i];
        }
        sLab = blockReduceSumD(sLab, shd);
        sCe  = blockReduceSumD(sCe,  shd);
        sMse = blockReduceSumD(sMse, shd);
        if (threadIdx.x == 0) {
            double loss_labels = sLab / ((double)B * (double)NROW);
            double loss_ce     = sCe / (double)(QDIM - 1);
            double loss_mse    = sMse / (double)B;
            out[0] = (float)loss_labels;
            out[1] = (float)(loss_ce * 200.0 + loss_mse);
            g_count = 0;   // reset for next graph replay
        }
    }
    (void)rowStats;
}

extern "C" void kernel_launch(void* const* d_in, const int* in_sizes, int n_in,
                              void* d_out, int out_size) {
    const float* pred_legal   = (const float*)d_in[0];
    const float* pred_q       = (const float*)d_in[1];
    const float* target_legal = (const float*)d_in[2];
    const float* target_q     = (const float*)d_in[3];
    float* out = (float*)d_out;

    int B = in_sizes[1] / QDIM;   // 4096

    crit_kernel<<<B, 256>>>((const float4*)pred_legal,
                            (const float4*)target_legal,
                            (const float4*)pred_q,
                            (const float4*)target_q,
                            out, B);
}

// round 7
// speedup vs baseline: 1.1238x; 1.0776x over previous
#include <cuda_runtime.h>
#include <math.h>
#include <cstdint>

#define NROW 4096          // 64*64 legality cells per board
#define QDIM 256           // quality vector length
#define NEG_FILL -1000000.0f
#define EOS_COEF 0.25f
#define MAXROWS 8192

// Per-row partials + ticket (static globals — no allocation)
__device__ float    g_lab[MAXROWS];
__device__ float    g_ce [MAXROWS];
__device__ float    g_mse[MAXROWS];
__device__ unsigned g_count;   // zero-init; last block resets to 0

// spread 8 bits to every 4th bit position (bit i -> bit 4i)
__device__ __forceinline__ unsigned spread4(unsigned x) {
    x = (x | (x << 12)) & 0x000F000Fu;
    x = (x | (x << 6))  & 0x03030303u;
    x = (x | (x << 3))  & 0x11111111u;
    return x;
}

__device__ __forceinline__ float warpSum(float v) {
    #pragma unroll
    for (int o = 16; o; o >>= 1) v += __shfl_xor_sync(0xffffffffu, v, o);
    return v;
}
__device__ __forceinline__ float warpMax(float v) {
    #pragma unroll
    for (int o = 16; o; o >>= 1) v = fmaxf(v, __shfl_xor_sync(0xffffffffu, v, o));
    return v;
}
__device__ __forceinline__ double blockReduceSumD(double v, double* shd) {
    int lane = threadIdx.x & 31, warp = threadIdx.x >> 5;
    #pragma unroll
    for (int o = 16; o; o >>= 1) v += __shfl_down_sync(0xffffffffu, v, o);
    if (lane == 0) shd[warp] = v;
    __syncthreads();
    if (warp == 0) {
        v = (lane < 8) ? shd[lane] : 0.0;
        #pragma unroll
        for (int o = 4; o; o >>= 1) v += __shfl_down_sync(0xffffffffu, v, o);
        if (lane == 0) shd[0] = v;
    }
    __syncthreads();
    double r = shd[0];
    __syncthreads();
    return r;
}

__device__ __forceinline__ uint32_t smem_u32(const void* p) {
    return (uint32_t)__cvta_generic_to_shared(p);
}

// One block per batch row. Bulk-async copy of the 32 KB legality tiles into
// shared (register-free MLP), then compute from LDS.
__global__ __launch_bounds__(256) void crit_kernel(
    const float* __restrict__ pl,     // pred_legal  [B,4096]
    const float* __restrict__ tl,     // target_legal[B,4096]
    const float4* __restrict__ pq4,   // pred_q      [B*64] float4
    const float4* __restrict__ tq4,   // target_q    [B*64] float4
    float* __restrict__ out, int B)
{
    const int b = blockIdx.x;
    const int w = threadIdx.x >> 5, l = threadIdx.x & 31;

    __shared__ alignas(128) float sP[NROW];      // 16 KB
    __shared__ alignas(128) float sT[NROW];      // 16 KB
    __shared__ alignas(16)  unsigned long long mbar;
    __shared__ alignas(16)  float pqs[QDIM], tqs[QDIM];       // float4-accessed
    __shared__ alignas(16)  unsigned maskT[128], maskP[128];  // uint4-accessed
    __shared__ float lined[QDIM];
    __shared__ unsigned char match[QDIM];
    __shared__ float red[8];
    __shared__ double shd[8];
    __shared__ unsigned lastFlag;

    const uint32_t mb = smem_u32(&mbar);

    if (threadIdx.x == 0) {
        asm volatile("mbarrier.init.shared.b64 [%0], %1;"
                     :: "r"(mb), "r"(1u) : "memory");
    }
    __syncthreads();

    if (threadIdx.x == 0) {
        // one arrival + 32 KB of expected transactions
        asm volatile("mbarrier.arrive.expect_tx.shared.b64 _, [%0], %1;"
                     :: "r"(mb), "r"(32768u) : "memory");
        const float* srcP = pl + (size_t)b * NROW;
        const float* srcT = tl + (size_t)b * NROW;
        asm volatile(
            "cp.async.bulk.shared::cluster.global.mbarrier::complete_tx::bytes"
            " [%0], [%1], %2, [%3];"
            :: "r"(smem_u32(sP)), "l"(srcP), "r"(16384u), "r"(mb) : "memory");
        asm volatile(
            "cp.async.bulk.shared::cluster.global.mbarrier::complete_tx::bytes"
            " [%0], [%1], %2, [%3];"
            :: "r"(smem_u32(sT)), "l"(srcT), "r"(16384u), "r"(mb) : "memory");
    }

    // stage quality rows into shared while bulk copies fly
    if (threadIdx.x < 64)
        ((float4*)pqs)[threadIdx.x] = pq4[(size_t)b * 64 + threadIdx.x];
    else if (threadIdx.x < 128)
        ((float4*)tqs)[threadIdx.x - 64] = tq4[(size_t)b * 64 + (threadIdx.x - 64)];

    // wait for the 32 KB (fresh barrier each launch -> parity 0)
    {
        uint32_t done;
        asm volatile(
            "{\n\t.reg .pred p;\n\t"
            "mbarrier.try_wait.parity.acquire.cta.shared::cta.b64 p, [%1], %2;\n\t"
            "selp.b32 %0, 1, 0, p;\n\t}"
            : "=r"(done) : "r"(mb), "r"(0u) : "memory");
        if (!done) {
            asm volatile(
                "{\n\t.reg .pred P1;\n\t"
                "WAIT_LOOP_%=:\n\t"
                "mbarrier.try_wait.parity.acquire.cta.shared::cta.b64 P1, [%0], %1, 0x989680;\n\t"
                "@P1 bra.uni WAIT_DONE_%=;\n\t"
                "bra.uni WAIT_LOOP_%=;\n\t"
                "WAIT_DONE_%=:\n\t}"
                :: "r"(mb), "r"(0u) : "memory");
        }
    }

    // ---- compute from shared: warp w covers elements [512w, 512w+512) ----
    const float4* sP4 = (const float4*)sP;
    const float4* sT4 = (const float4*)sT;
    float acc = 0.f;
    #pragma unroll
    for (int i = 0; i < 4; i++) {
        int idx = w * 128 + i * 32 + l;
        float4 pv = sP4[idx];
        float4 tv = sT4[idx];
        float px[4] = {pv.x, pv.y, pv.z, pv.w};
        float tx[4] = {tv.x, tv.y, tv.z, tv.w};
        bool pt[4], pp[4];
        #pragma unroll
        for (int j = 0; j < 4; j++) {
            float x = px[j], tg = tx[j];
            float sp  = __logf(1.f + __expf(-fabsf(x)));   // fast ok in BCE (R3)
            float bce = fmaxf(x, 0.f) - x * tg + sp;
            acc += (tg == 0.f ? EOS_COEF : 1.f) * bce;
            pt[j] = (tg == 1.f);
            pp[j] = (x  > 0.f);
        }
        // ballot word j: bit l = element (chunkBase + 4l + j)
        unsigned bT0 = __ballot_sync(0xffffffffu, pt[0]);
        unsigned bT1 = __ballot_sync(0xffffffffu, pt[1]);
        unsigned bT2 = __ballot_sync(0xffffffffu, pt[2]);
        unsigned bT3 = __ballot_sync(0xffffffffu, pt[3]);
        unsigned bP0 = __ballot_sync(0xffffffffu, pp[0]);
        unsigned bP1 = __ballot_sync(0xffffffffu, pp[1]);
        unsigned bP2 = __ballot_sync(0xffffffffu, pp[2]);
        unsigned bP3 = __ballot_sync(0xffffffffu, pp[3]);
        int base = w * 16 + i * 4;
        if (l < 4) {
            unsigned vT = (l == 0) ? bT0 : (l == 1) ? bT1 : (l == 2) ? bT2 : bT3;
            maskT[base + l] = vT;
        } else if (l < 8) {
            int j = l - 4;
            unsigned vP = (j == 0) ? bP0 : (j == 1) ? bP1 : (j == 2) ? bP2 : bP3;
            maskP[base + j] = vP;
        }
    }
    acc = warpSum(acc);
    if (l == 0) red[w] = acc;
    __syncthreads();

    // ---- lineup: warp 0 only ----
    if (w == 0) {
        uint4 WT = ((const uint4*)maskT)[l];
        uint4 WP = ((const uint4*)maskP)[l];

        #pragma unroll
        for (int j = 0; j < 8; j++) {
            lined[l * 8 + j] = NEG_FILL;
            match[l * 8 + j] = 0;
        }

        // transpose ballot-order -> row-major words
        unsigned mT[4], mP[4];
        #pragma unroll
        for (int k = 0; k < 4; k++) {
            unsigned s = 8 * k;
            mT[k] = spread4((WT.x >> s) & 0xFFu)
                  | (spread4((WT.y >> s) & 0xFFu) << 1)
                  | (spread4((WT.z >> s) & 0xFFu) << 2)
                  | (spread4((WT.w >> s) & 0xFFu) << 3);
            mP[k] = spread4((WP.x >> s) & 0xFFu)
                  | (spread4((WP.y >> s) & 0xFFu) << 1)
                  | (spread4((WP.z >> s) & 0xFFu) << 2)
                  | (spread4((WP.w >> s) & 0xFFu) << 3);
        }

        int cT = 0, cP = 0;
        #pragma unroll
        for (int k = 0; k < 4; k++) { cT += __popc(mT[k]); cP += __popc(mP[k]); }
        int sTc = cT, sPc = cP;
        #pragma unroll
        for (int o = 1; o < 32; o <<= 1) {
            int vT = __shfl_up_sync(0xffffffffu, sTc, o);
            int vP = __shfl_up_sync(0xffffffffu, sPc, o);
            if (l >= o) { sTc += vT; sPc += vP; }
        }
        int tIdx  = sTc - cT;
        int pBase = sPc - cP;
        __syncwarp();

        #pragma unroll
        for (int k = 0; k < 4; k++) {
            unsigned m = mT[k], p = mP[k];
            while (m) {
                int bit = __ffs(m) - 1;
                m &= m - 1;
                if ((p >> bit) & 1u) {
                    int pi = pBase + __popc(p & ((1u << bit) - 1u));
                    if (pi < QDIM - 1 && tIdx < QDIM - 1) {
                        lined[tIdx] = pqs[pi];
                        match[tIdx] = 1;
                    }
                }
                tIdx++;
            }
            pBase += __popc(p);
        }
        __syncwarp();

        // logsumexp over lined[0..254] — PRECISE expf/logf (CE is x200 sensitive)
        float vals[8];
        float mx = -INFINITY;
        #pragma unroll
        for (int j = 0; j < 8; j++) {
            vals[j] = lined[l * 8 + j];
            mx = fmaxf(mx, vals[j]);
        }
        mx = warpMax(mx);
        float es = 0.f;
        #pragma unroll
        for (int j = 0; j < 8; j++)
            if (l * 8 + j < QDIM - 1) es += expf(vals[j] - mx);
        es = warpSum(es);
        float lse = mx + logf(es);

        float wsum = 0.f, dot = 0.f;
        #pragma unroll
        for (int j = 0; j < 8; j++) {
            int idx = l * 8 + j;
            if (idx < QDIM - 1) {
                float wq = tqs[idx] * (float)match[idx];
                wsum += wq;
                dot  += wq * (vals[j] - lse);
            }
        }
        wsum = warpSum(wsum);
        dot  = warpSum(dot);

        if (l == 0) {
            float ce = -dot / (wsum + 1e-10f);
            float dq = pqs[QDIM - 1] - tqs[QDIM - 1];
            float lab = 0.f;
            #pragma unroll
            for (int i = 0; i < 8; i++) lab += red[i];
            g_lab[b] = lab;
            g_ce [b] = ce;
            g_mse[b] = dq * dq;
            __threadfence();
            unsigned old = atomicAdd(&g_count, 1u);
            lastFlag = (old == (unsigned)(B - 1)) ? 1u : 0u;
        }
    }
    __syncthreads();

    // ---- last block: final scalar reduce ----
    if (lastFlag) {
        __threadfence();
        double sLab = 0.0, sCe = 0.0, sMse = 0.0;
        for (int i = threadIdx.x; i < B; i += 256) {
            sLab += (double)g_lab[i];
            sCe  += (double)g_ce[i];
            sMse += (double)g_mse[i];
        }
        sLab = blockReduceSumD(sLab, shd);
        sCe  = blockReduceSumD(sCe,  shd);
        sMse = blockReduceSumD(sMse, shd);
        if (threadIdx.x == 0) {
            double loss_labels = sLab / ((double)B * (double)NROW);
            double loss_ce     = sCe / (double)(QDIM - 1);
            double loss_mse    = sMse / (double)B;
            out[0] = (float)loss_labels;
            out[1] = (float)(loss_ce * 200.0 + loss_mse);
            g_count = 0;   // reset for next graph replay
        }
    }
}

extern "C" void kernel_launch(void* const* d_in, const int* in_sizes, int n_in,
                              void* d_out, int out_size) {
    const float* pred_legal   = (const float*)d_in[0];
    const float* pred_q       = (const float*)d_in[1];
    const float* target_legal = (const float*)d_in[2];
    const float* target_q     = (const float*)d_in[3];
    float* out = (float*)d_out;

    int B = in_sizes[1] / QDIM;   // 4096

    crit_kernel<<<B, 256>>>(pred_legal, target_legal,
                            (const float4*)pred_q,
                            (const float4*)target_q,
                            out, B);
}